// round 2
// baseline (speedup 1.0000x reference)
#include <cuda_runtime.h>
#include <cuda_bf16.h>
#include <math.h>

// Shapes (fixed for this problem)
#define B_ 2
#define S_ 2048
#define C_ 2048
#define H_ 32
#define HD 64
#define C3 6144          // 3*C_
#define BS (B_*S_)       // 4096 rows

// Scratch (device globals: allocation-free)
__device__ float g_qkv[BS * C3];    // [b*s][h*192 + {q,k,v}*64 + d]  (~100.7 MB)
__device__ float g_att[BS * C_];    // attention output [b*s][h*64+d] (~33.5 MB)

// ---------------------------------------------------------------------------
// SGEMM: C[m][n] = sum_k A[m*K+k] * B[n*K+k]   (A row-major MxK, B row-major NxK)
// 128x128 tile, BK=16, 256 threads, 8x8 per thread (split 4+4).
// M,N multiples of 128; K multiple of 16 (true for both GEMMs here).
// ---------------------------------------------------------------------------
__global__ __launch_bounds__(256) void sgemm_abt(
    const float* __restrict__ A, const float* __restrict__ Bw,
    float* __restrict__ C, int M, int N, int K)
{
    __shared__ float As[16][128];
    __shared__ float Bs[16][128];

    const int tid = threadIdx.x;
    const int tx = tid & 15;         // 0..15
    const int ty = tid >> 4;         // 0..15
    const int m0 = blockIdx.y * 128;
    const int n0 = blockIdx.x * 128;

    float acc[8][8];
#pragma unroll
    for (int i = 0; i < 8; i++)
#pragma unroll
        for (int j = 0; j < 8; j++) acc[i][j] = 0.f;

    for (int k0 = 0; k0 < K; k0 += 16) {
#pragma unroll
        for (int i = 0; i < 2; i++) {
            int lin = tid + i * 256;          // 0..511
            int row = lin >> 2;               // 0..127
            int kc  = (lin & 3) * 4;          // 0,4,8,12
            float4 va = *(const float4*)&A[(m0 + row) * K + k0 + kc];
            As[kc + 0][row] = va.x; As[kc + 1][row] = va.y;
            As[kc + 2][row] = va.z; As[kc + 3][row] = va.w;
            float4 vb = *(const float4*)&Bw[(n0 + row) * K + k0 + kc];
            Bs[kc + 0][row] = vb.x; Bs[kc + 1][row] = vb.y;
            Bs[kc + 2][row] = vb.z; Bs[kc + 3][row] = vb.w;
        }
        __syncthreads();

#pragma unroll
        for (int k = 0; k < 16; k++) {
            float4 a0 = *(const float4*)&As[k][ty * 4];
            float4 a1 = *(const float4*)&As[k][ty * 4 + 64];
            float4 b0 = *(const float4*)&Bs[k][tx * 4];
            float4 b1 = *(const float4*)&Bs[k][tx * 4 + 64];
            float ar[8] = {a0.x, a0.y, a0.z, a0.w, a1.x, a1.y, a1.z, a1.w};
            float br[8] = {b0.x, b0.y, b0.z, b0.w, b1.x, b1.y, b1.z, b1.w};
#pragma unroll
            for (int i = 0; i < 8; i++)
#pragma unroll
                for (int j = 0; j < 8; j++) acc[i][j] = fmaf(ar[i], br[j], acc[i][j]);
        }
        __syncthreads();
    }

#pragma unroll
    for (int i = 0; i < 8; i++) {
        int row = m0 + ((i < 4) ? (ty * 4 + i) : (64 + ty * 4 + i - 4));
        float4 c0 = make_float4(acc[i][0], acc[i][1], acc[i][2], acc[i][3]);
        float4 c1 = make_float4(acc[i][4], acc[i][5], acc[i][6], acc[i][7]);
        *(float4*)&C[row * N + n0 + tx * 4]      = c0;
        *(float4*)&C[row * N + n0 + 64 + tx * 4] = c1;
    }
}

// ---------------------------------------------------------------------------
// LayerNorm (per-head, hd=64, eps=1e-5, biased var) + rotary, in-place on q,k.
// One warp per (token, head, which). 262144 warps total.
// ---------------------------------------------------------------------------
__global__ __launch_bounds__(256) void ln_rope_kernel(
    float* __restrict__ qkv, const float* __restrict__ rope,
    const float* __restrict__ qg, const float* __restrict__ qb,
    const float* __restrict__ kg, const float* __restrict__ kb)
{
    int wid  = (blockIdx.x * blockDim.x + threadIdx.x) >> 5;
    int lane = threadIdx.x & 31;
    int which = wid & 1;          // 0=q, 1=k
    int rowh  = wid >> 1;         // (b*S+s)*32 + h
    int h  = rowh & 31;
    int bs = rowh >> 5;           // b*S + s
    int s  = bs & (S_ - 1);

    float* p = qkv + bs * C3 + h * 192 + which * 64;
    float x0 = p[lane];
    float x1 = p[lane + 32];

    float sum = x0 + x1;
#pragma unroll
    for (int off = 16; off > 0; off >>= 1) sum += __shfl_xor_sync(0xffffffffu, sum, off);
    float mean = sum * (1.0f / 64.0f);
    float d0 = x0 - mean, d1 = x1 - mean;
    float vs = d0 * d0 + d1 * d1;
#pragma unroll
    for (int off = 16; off > 0; off >>= 1) vs += __shfl_xor_sync(0xffffffffu, vs, off);
    float rstd = rsqrtf(vs * (1.0f / 64.0f) + 1e-5f);

    const float* g  = which ? kg : qg;
    const float* bt = which ? kb : qb;
    float y0 = d0 * rstd * g[lane]      + bt[lane];
    float y1 = d1 * rstd * g[lane + 32] + bt[lane + 32];

    // rotary: pairs (2i, 2i+1); partner element lives in lane^1
    float pr0 = __shfl_xor_sync(0xffffffffu, y0, 1);
    float pr1 = __shfl_xor_sync(0xffffffffu, y1, 1);
    int j = lane & 1;                // parity of d (same for d=lane and d=lane+32)
    const float* rb = rope + s * 128;

    int i0 = lane >> 1;
    float e0 = j ? pr0 : y0;         // x[2i]
    float o0 = j ? y0 : pr0;         // x[2i+1]
    float out0 = rb[i0 * 4 + j * 2 + 0] * e0 + rb[i0 * 4 + j * 2 + 1] * o0;

    int i1 = (lane + 32) >> 1;
    float e1 = j ? pr1 : y1;
    float o1 = j ? y1 : pr1;
    float out1 = rb[i1 * 4 + j * 2 + 0] * e1 + rb[i1 * 4 + j * 2 + 1] * o1;

    p[lane]      = out0;
    p[lane + 32] = out1;
}

// ---------------------------------------------------------------------------
// Flash attention (non-causal, scale=1/8). Block = 64 query rows of one (b,h).
// 256 threads: thread = (row r = tid>>2, part = tid&3).
//   scores: thread handles cols c = cc*4+part (cc=0..15), q cached in regs.
//   PV:     thread accumulates d-chunks chunk = 4j+part (d = 16j+4*part+e).
// Smem pitches = 68 floats -> conflict-free broadcast LDS (bank math verified).
// ---------------------------------------------------------------------------
#define PITCH 68
#define ATT_SMEM (3 * 64 * PITCH * 4)   // 52224 bytes

__global__ __launch_bounds__(256) void attn_kernel(
    const float* __restrict__ qkv, float* __restrict__ o)
{
    extern __shared__ float sm[];
    float* Ks = sm;                    // [64][PITCH]
    float* Vs = sm + 64 * PITCH;       // [64][PITCH]
    float* Ss = sm + 2 * 64 * PITCH;   // [64][PITCH]

    const int tid  = threadIdx.x;
    const int r    = tid >> 2;         // query row within tile, 0..63
    const int part = tid & 3;
    const int qt = blockIdx.x;         // 0..31
    const int h  = blockIdx.y;         // 0..31
    const int b  = blockIdx.z;         // 0..1

    const int qrow = qt * 64 + r;
    const float* qptr = qkv + (b * S_ + qrow) * C3 + h * 192;

    float4 qreg[16];
#pragma unroll
    for (int i = 0; i < 16; i++) qreg[i] = *(const float4*)(qptr + i * 4);

    float m = -1e30f, l = 0.f;
    float acc[16];
#pragma unroll
    for (int i = 0; i < 16; i++) acc[i] = 0.f;

    for (int kv0 = 0; kv0 < S_; kv0 += 64) {
        __syncthreads();   // previous tile's PV done reading Vs/Ss

        // load K and V tiles (coalesced, 4 float4 per thread per tensor)
#pragma unroll
        for (int i = 0; i < 4; i++) {
            int lin = tid + i * 256;     // 0..1023
            int row = lin >> 4;          // 0..63
            int c4  = lin & 15;          // 0..15
            const float* base = qkv + (b * S_ + kv0 + row) * C3 + h * 192;
            *(float4*)&Ks[row * PITCH + c4 * 4] = *(const float4*)(base + 64  + c4 * 4);
            *(float4*)&Vs[row * PITCH + c4 * 4] = *(const float4*)(base + 128 + c4 * 4);
        }
        __syncthreads();

        // ---- scores ----
        float s[16];
        float tmax = -1e30f;
#pragma unroll
        for (int cc = 0; cc < 16; cc++) {
            int c = cc * 4 + part;
            const float4* kr = (const float4*)&Ks[c * PITCH];
            float as = 0.f;
#pragma unroll
            for (int d4 = 0; d4 < 16; d4++) {
                float4 kv = kr[d4];
                float4 qv = qreg[d4];
                as = fmaf(qv.x, kv.x, as);
                as = fmaf(qv.y, kv.y, as);
                as = fmaf(qv.z, kv.z, as);
                as = fmaf(qv.w, kv.w, as);
            }
            s[cc] = as * 0.125f;
            tmax = fmaxf(tmax, s[cc]);
        }
        tmax = fmaxf(tmax, __shfl_xor_sync(0xffffffffu, tmax, 1));
        tmax = fmaxf(tmax, __shfl_xor_sync(0xffffffffu, tmax, 2));

        float mnew = fmaxf(m, tmax);
        float corr = __expf(m - mnew);
        float lsum = 0.f;
#pragma unroll
        for (int cc = 0; cc < 16; cc++) {
            float pv = __expf(s[cc] - mnew);
            lsum += pv;
            Ss[r * PITCH + cc * 4 + part] = pv;
        }
        lsum += __shfl_xor_sync(0xffffffffu, lsum, 1);
        lsum += __shfl_xor_sync(0xffffffffu, lsum, 2);
        l = l * corr + lsum;
        m = mnew;
#pragma unroll
        for (int i = 0; i < 16; i++) acc[i] *= corr;
        __syncthreads();   // Ss visible to whole block; Ks reads finished

        // ---- PV ----
#pragma unroll 8
        for (int c = 0; c < 64; c++) {
            float pv = Ss[r * PITCH + c];
#pragma unroll
            for (int j = 0; j < 4; j++) {
                float4 v = *(const float4*)&Vs[c * PITCH + (4 * j + part) * 4];
                acc[4 * j + 0] = fmaf(pv, v.x, acc[4 * j + 0]);
                acc[4 * j + 1] = fmaf(pv, v.y, acc[4 * j + 1]);
                acc[4 * j + 2] = fmaf(pv, v.z, acc[4 * j + 2]);
                acc[4 * j + 3] = fmaf(pv, v.w, acc[4 * j + 3]);
            }
        }
    }

    float inv = 1.0f / l;
    float* optr = o + (b * S_ + qrow) * C_ + h * 64;
#pragma unroll
    for (int j = 0; j < 4; j++) {
        float4 v = make_float4(acc[4 * j] * inv, acc[4 * j + 1] * inv,
                               acc[4 * j + 2] * inv, acc[4 * j + 3] * inv);
        *(float4*)(optr + 16 * j + 4 * part) = v;
    }
}

// ---------------------------------------------------------------------------
extern "C" void kernel_launch(void* const* d_in, const int* in_sizes, int n_in,
                              void* d_out, int out_size)
{
    const float* x     = (const float*)d_in[0];
    const float* rope  = (const float*)d_in[1];
    const float* w_qkv = (const float*)d_in[2];
    const float* w_out = (const float*)d_in[3];
    const float* qg    = (const float*)d_in[4];
    const float* qb    = (const float*)d_in[5];
    const float* kg    = (const float*)d_in[6];
    const float* kb    = (const float*)d_in[7];
    float* out = (float*)d_out;

    // not a stream op; safe under graph capture, needed for 51 KB dynamic smem
    cudaFuncSetAttribute(attn_kernel, cudaFuncAttributeMaxDynamicSharedMemorySize, ATT_SMEM);

    float* qkv = nullptr;
    float* att = nullptr;
    cudaGetSymbolAddress((void**)&qkv, g_qkv);
    cudaGetSymbolAddress((void**)&att, g_att);

    // 1) QKV projection: [4096,2048] x [6144,2048]^T -> [4096,6144]
    sgemm_abt<<<dim3(C3 / 128, BS / 128), 256>>>(x, w_qkv, qkv, BS, C3, C_);

    // 2) per-head LN + rotary on q,k (in place)
    ln_rope_kernel<<<(BS * H_ * 2) / 8, 256>>>(qkv, rope, qg, qb, kg, kb);

    // 3) flash attention
    attn_kernel<<<dim3(S_ / 64, H_, B_), 256, ATT_SMEM>>>(qkv, att);

    // 4) output projection: [4096,2048] x [2048,2048]^T -> d_out
    sgemm_abt<<<dim3(C_ / 128, BS / 128), 256>>>(att, w_out, out, BS, C_, C_);
}

// round 5
// speedup vs baseline: 2.9601x; 2.9601x over previous
#include <cuda_runtime.h>
#include <cuda_bf16.h>
#include <cstdint>
#include <math.h>

#define B_ 2
#define S_ 2048
#define C_ 2048
#define H_ 32
#define C3 6144
#define BS (B_*S_)

// Scratch (allocation-free device globals)
__device__ float g_qkv[BS * C3];
__device__ __nv_bfloat16 g_xhi[BS * C_],  g_xlo[BS * C_];
__device__ __nv_bfloat16 g_wqhi[C3 * C_], g_wqlo[C3 * C_];
__device__ __nv_bfloat16 g_wohi[C_ * C_], g_wolo[C_ * C_];
__device__ __nv_bfloat16 g_qhi[BS * C_],  g_qlo[BS * C_];
__device__ __nv_bfloat16 g_khi[BS * C_],  g_klo[BS * C_];
__device__ __nv_bfloat16 g_vthi[(size_t)B_ * H_ * 64 * S_], g_vtlo[(size_t)B_ * H_ * 64 * S_];
__device__ __nv_bfloat16 g_atthi[BS * C_], g_attlo[BS * C_];

__device__ __forceinline__ void mma_bf16(float4 &d,
    uint32_t a0, uint32_t a1, uint32_t a2, uint32_t a3, uint32_t b0, uint32_t b1)
{
    asm volatile("mma.sync.aligned.m16n8k16.row.col.f32.bf16.bf16.f32 "
        "{%0,%1,%2,%3}, {%4,%5,%6,%7}, {%8,%9}, {%0,%1,%2,%3};"
        : "+f"(d.x), "+f"(d.y), "+f"(d.z), "+f"(d.w)
        : "r"(a0), "r"(a1), "r"(a2), "r"(a3), "r"(b0), "r"(b1));
}

__device__ __forceinline__ uint32_t pack2(__nv_bfloat16 a, __nv_bfloat16 b) {
    __nv_bfloat162 t; t.x = a; t.y = b;
    return *reinterpret_cast<uint32_t*>(&t);
}

__device__ __forceinline__ void split2(float a, float b, uint32_t &hi, uint32_t &lo) {
    __nv_bfloat16 ha = __float2bfloat16_rn(a), hb = __float2bfloat16_rn(b);
    __nv_bfloat16 la = __float2bfloat16_rn(a - __bfloat162float(ha));
    __nv_bfloat16 lb = __float2bfloat16_rn(b - __bfloat162float(hb));
    hi = pack2(ha, hb); lo = pack2(la, lb);
}

// fp32 -> hi/lo bf16 split
__global__ __launch_bounds__(256) void split_kernel(
    const float* __restrict__ in, __nv_bfloat16* __restrict__ hi,
    __nv_bfloat16* __restrict__ lo, int n4)
{
    int i = blockIdx.x * blockDim.x + threadIdx.x;
    if (i >= n4) return;
    float4 v = ((const float4*)in)[i];
    uint32_t h0, l0, h1, l1;
    split2(v.x, v.y, h0, l0);
    split2(v.z, v.w, h1, l1);
    uint32_t* hi32 = (uint32_t*)hi;
    uint32_t* lo32 = (uint32_t*)lo;
    hi32[2*i] = h0; hi32[2*i+1] = h1;
    lo32[2*i] = l0; lo32[2*i+1] = l1;
}

// ---------------------------------------------------------------------------
// bf16x3 GEMM: C[m][n] = sum_k A[m][k]*B[n][k]. Word = bf16 pair, 16 words/row/BK32.
// Word w stored at ((w&3)^(row&3))*4 + (w>>2); uint4 frag load -> words {c,c+4,c+8,c+12}.
// ---------------------------------------------------------------------------
#define GEMM_SMEM (8 * 2048 * 4)

__global__ __launch_bounds__(256) void gemm_bf16x3(
    const __nv_bfloat16* __restrict__ Ahi, const __nv_bfloat16* __restrict__ Alo,
    const __nv_bfloat16* __restrict__ Bhi, const __nv_bfloat16* __restrict__ Blo,
    float* __restrict__ C, int M, int N, int K)
{
    extern __shared__ uint32_t gsm[];
#define SG(buf, arr) (gsm + ((buf) * 4 + (arr)) * 2048)

    const int tid  = threadIdx.x;
    const int lane = tid & 31, wid = tid >> 5;
    const int g = lane >> 2, c = lane & 3;
    const int wm = wid >> 2, wn = wid & 3;
    const int m0 = blockIdx.y * 128, n0 = blockIdx.x * 128;
    const int lrow = tid >> 2, lkc = tid & 3;
    const int rsu  = K >> 3;   // uint4 per row

    const uint4* GA[2] = { (const uint4*)Ahi, (const uint4*)Alo };
    const uint4* GB[2] = { (const uint4*)Bhi, (const uint4*)Blo };

    float4 d[4][4];
#pragma unroll
    for (int i = 0; i < 4; i++)
#pragma unroll
        for (int j = 0; j < 4; j++) d[i][j] = make_float4(0.f, 0.f, 0.f, 0.f);

    uint4 pf[8];
#pragma unroll
    for (int hl = 0; hl < 2; hl++)
#pragma unroll
        for (int i = 0; i < 2; i++) {
            int row = lrow + i * 64;
            pf[hl*2 + i]     = GA[hl][(size_t)(m0 + row) * rsu + lkc];
            pf[4 + hl*2 + i] = GB[hl][(size_t)(n0 + row) * rsu + lkc];
        }
#pragma unroll
    for (int hl = 0; hl < 2; hl++)
#pragma unroll
        for (int i = 0; i < 2; i++) {
            int row = lrow + i * 64; int sw = row & 3; int base = row * 16;
            uint4 va = pf[hl*2 + i], vb = pf[4 + hl*2 + i];
            uint32_t* Sa = SG(0, hl); uint32_t* Sb = SG(0, 2 + hl);
            Sa[base + ((0^sw)<<2) + lkc] = va.x; Sa[base + ((1^sw)<<2) + lkc] = va.y;
            Sa[base + ((2^sw)<<2) + lkc] = va.z; Sa[base + ((3^sw)<<2) + lkc] = va.w;
            Sb[base + ((0^sw)<<2) + lkc] = vb.x; Sb[base + ((1^sw)<<2) + lkc] = vb.y;
            Sb[base + ((2^sw)<<2) + lkc] = vb.z; Sb[base + ((3^sw)<<2) + lkc] = vb.w;
        }
    __syncthreads();

    const int nit = K >> 5;
    for (int it = 0; it < nit; it++) {
        const int cur = it & 1;
        if (it + 1 < nit) {
            const int ko = (it + 1) * 4;
#pragma unroll
            for (int hl = 0; hl < 2; hl++)
#pragma unroll
                for (int i = 0; i < 2; i++) {
                    int row = lrow + i * 64;
                    pf[hl*2 + i]     = GA[hl][(size_t)(m0 + row) * rsu + ko + lkc];
                    pf[4 + hl*2 + i] = GB[hl][(size_t)(n0 + row) * rsu + ko + lkc];
                }
        }

        const uint32_t* SAh = SG(cur, 0); const uint32_t* SAl = SG(cur, 1);
        const uint32_t* SBh = SG(cur, 2); const uint32_t* SBl = SG(cur, 3);

        uint4 bh[4], bl[4];
#pragma unroll
        for (int in_ = 0; in_ < 4; in_++) {
            int n = wn * 32 + in_ * 8 + g;
            int off = n * 16 + ((c ^ (n & 3)) << 2);
            bh[in_] = *(const uint4*)&SBh[off];
            bl[in_] = *(const uint4*)&SBl[off];
        }
#pragma unroll
        for (int im = 0; im < 4; im++) {
            int r = wm * 64 + im * 16 + g;
            int off0 = r * 16 + ((c ^ (r & 3)) << 2);
            int off1 = (r + 8) * 16 + (((c) ^ ((r + 8) & 3)) << 2);
            uint4 ah0 = *(const uint4*)&SAh[off0];
            uint4 ah1 = *(const uint4*)&SAh[off1];
            uint4 al0 = *(const uint4*)&SAl[off0];
            uint4 al1 = *(const uint4*)&SAl[off1];
#pragma unroll
            for (int in_ = 0; in_ < 4; in_++) {
                mma_bf16(d[im][in_], ah0.x, ah1.x, ah0.y, ah1.y, bh[in_].x, bh[in_].y);
                mma_bf16(d[im][in_], ah0.x, ah1.x, ah0.y, ah1.y, bl[in_].x, bl[in_].y);
                mma_bf16(d[im][in_], al0.x, al1.x, al0.y, al1.y, bh[in_].x, bh[in_].y);
                mma_bf16(d[im][in_], ah0.z, ah1.z, ah0.w, ah1.w, bh[in_].z, bh[in_].w);
                mma_bf16(d[im][in_], ah0.z, ah1.z, ah0.w, ah1.w, bl[in_].z, bl[in_].w);
                mma_bf16(d[im][in_], al0.z, al1.z, al0.w, al1.w, bh[in_].z, bh[in_].w);
            }
        }

        if (it + 1 < nit) {
#pragma unroll
            for (int hl = 0; hl < 2; hl++)
#pragma unroll
                for (int i = 0; i < 2; i++) {
                    int row = lrow + i * 64; int sw = row & 3; int base = row * 16;
                    uint4 va = pf[hl*2 + i], vb = pf[4 + hl*2 + i];
                    uint32_t* Sa = SG(cur ^ 1, hl); uint32_t* Sb = SG(cur ^ 1, 2 + hl);
                    Sa[base + ((0^sw)<<2) + lkc] = va.x; Sa[base + ((1^sw)<<2) + lkc] = va.y;
                    Sa[base + ((2^sw)<<2) + lkc] = va.z; Sa[base + ((3^sw)<<2) + lkc] = va.w;
                    Sb[base + ((0^sw)<<2) + lkc] = vb.x; Sb[base + ((1^sw)<<2) + lkc] = vb.y;
                    Sb[base + ((2^sw)<<2) + lkc] = vb.z; Sb[base + ((3^sw)<<2) + lkc] = vb.w;
                }
        }
        __syncthreads();
    }

#pragma unroll
    for (int im = 0; im < 4; im++)
#pragma unroll
        for (int in_ = 0; in_ < 4; in_++) {
            int row = m0 + wm * 64 + im * 16 + g;
            int col = n0 + wn * 32 + in_ * 8 + 2 * c;
            *(float2*)&C[(size_t)row * N + col]       = make_float2(d[im][in_].x, d[im][in_].y);
            *(float2*)&C[(size_t)(row + 8) * N + col] = make_float2(d[im][in_].z, d[im][in_].w);
        }
#undef SG
}

// ---------------------------------------------------------------------------
// LN (per-head) + rotary; q pre-scaled by 1/8; writes split bf16 q/k.
// ---------------------------------------------------------------------------
__global__ __launch_bounds__(256) void ln_rope_kernel(
    const float* __restrict__ qkv, const float* __restrict__ rope,
    const float* __restrict__ qg, const float* __restrict__ qb,
    const float* __restrict__ kg, const float* __restrict__ kb,
    __nv_bfloat16* __restrict__ qhi, __nv_bfloat16* __restrict__ qlo,
    __nv_bfloat16* __restrict__ khi, __nv_bfloat16* __restrict__ klo)
{
    int wid  = (blockIdx.x * blockDim.x + threadIdx.x) >> 5;
    int lane = threadIdx.x & 31;
    int which = wid & 1;
    int rowh  = wid >> 1;
    int h  = rowh & 31;
    int bs = rowh >> 5;
    int s  = bs & (S_ - 1);

    const float* p = qkv + (size_t)bs * C3 + h * 192 + which * 64;
    float x0 = p[lane];
    float x1 = p[lane + 32];

    float sum = x0 + x1;
#pragma unroll
    for (int off = 16; off > 0; off >>= 1) sum += __shfl_xor_sync(0xffffffffu, sum, off);
    float mean = sum * (1.0f / 64.0f);
    float d0 = x0 - mean, d1 = x1 - mean;
    float vs = d0 * d0 + d1 * d1;
#pragma unroll
    for (int off = 16; off > 0; off >>= 1) vs += __shfl_xor_sync(0xffffffffu, vs, off);
    float rstd = rsqrtf(vs * (1.0f / 64.0f) + 1e-5f);

    const float* gm = which ? kg : qg;
    const float* bt = which ? kb : qb;
    float y0 = d0 * rstd * gm[lane]      + bt[lane];
    float y1 = d1 * rstd * gm[lane + 32] + bt[lane + 32];

    float pr0 = __shfl_xor_sync(0xffffffffu, y0, 1);
    float pr1 = __shfl_xor_sync(0xffffffffu, y1, 1);
    int j = lane & 1;
    const float* rb = rope + s * 128;

    int i0 = lane >> 1;
    float e0 = j ? pr0 : y0;
    float o0 = j ? y0 : pr0;
    float out0 = rb[i0 * 4 + j * 2 + 0] * e0 + rb[i0 * 4 + j * 2 + 1] * o0;

    int i1 = (lane + 32) >> 1;
    float e1 = j ? pr1 : y1;
    float o1 = j ? y1 : pr1;
    float out1 = rb[i1 * 4 + j * 2 + 0] * e1 + rb[i1 * 4 + j * 2 + 1] * o1;

    if (which == 0) { out0 *= 0.125f; out1 *= 0.125f; }   // fold score scale into q

    __nv_bfloat16* hi = which ? khi : qhi;
    __nv_bfloat16* lo = which ? klo : qlo;
    size_t base = (size_t)bs * C_ + h * 64;
    __nv_bfloat16 h0 = __float2bfloat16_rn(out0);
    __nv_bfloat16 h1 = __float2bfloat16_rn(out1);
    hi[base + lane]      = h0;
    hi[base + lane + 32] = h1;
    lo[base + lane]      = __float2bfloat16_rn(out0 - __bfloat162float(h0));
    lo[base + lane + 32] = __float2bfloat16_rn(out1 - __bfloat162float(h1));
}

// ---------------------------------------------------------------------------
// V transpose + split: qkv v-slice [b][s][h][d] -> vt[b][h][d][s] bf16 hi/lo
// ---------------------------------------------------------------------------
__global__ __launch_bounds__(256) void vt_kernel(
    const float* __restrict__ qkv,
    __nv_bfloat16* __restrict__ vthi, __nv_bfloat16* __restrict__ vtlo)
{
    __shared__ __nv_bfloat16 shi[64][72];
    __shared__ __nv_bfloat16 slo[64][72];

    const int tid = threadIdx.x;
    const int s0 = blockIdx.x * 64, h = blockIdx.y, b = blockIdx.z;
    const int tok = tid >> 2, q = tid & 3;

#pragma unroll
    for (int it = 0; it < 4; it++) {
        int dd = q * 16 + it * 4;
        float4 v = *(const float4*)&qkv[(size_t)(b * S_ + s0 + tok) * C3 + h * 192 + 128 + dd];
        float vv[4] = {v.x, v.y, v.z, v.w};
#pragma unroll
        for (int j = 0; j < 4; j++) {
            __nv_bfloat16 hb = __float2bfloat16_rn(vv[j]);
            shi[dd + j][tok] = hb;
            slo[dd + j][tok] = __float2bfloat16_rn(vv[j] - __bfloat162float(hb));
        }
    }
    __syncthreads();

    const int dr = tid >> 2, cq = tid & 3;
    size_t gbase = ((size_t)(b * H_ + h) * 64 + dr) * S_ + s0 + cq * 16;
#pragma unroll
    for (int half = 0; half < 2; half++) {
        *(uint4*)&vthi[gbase + half * 8] = *(const uint4*)&shi[dr][cq * 16 + half * 8];
        *(uint4*)&vtlo[gbase + half * 8] = *(const uint4*)&slo[dr][cq * 16 + half * 8];
    }
}

// ---------------------------------------------------------------------------
// Flash attention, bf16x3. 128 q rows per block, 8 warps, warp-local softmax.
// Smem: K rows=tokens, Vt rows=d; 32 words/row, chunk XOR swizzle (conflict-free).
// ---------------------------------------------------------------------------
#define SW(row, ch) ((row) * 32 + (((ch) ^ ((row) & 7)) << 2))

__global__ __launch_bounds__(256) void attn_bf16x3(
    const __nv_bfloat16* __restrict__ qhi, const __nv_bfloat16* __restrict__ qlo,
    const __nv_bfloat16* __restrict__ khi, const __nv_bfloat16* __restrict__ klo,
    const __nv_bfloat16* __restrict__ vthi, const __nv_bfloat16* __restrict__ vtlo,
    __nv_bfloat16* __restrict__ atthi, __nv_bfloat16* __restrict__ attlo)
{
    __shared__ uint32_t sKh[2048], sKl[2048], sVh[2048], sVl[2048];

    const int tid = threadIdx.x, lane = tid & 31, wid = tid >> 5;
    const int g = lane >> 2, c = lane & 3;
    const int q0 = blockIdx.x * 128;
    const int h = blockIdx.y, b = blockIdx.z;
    const int w16 = wid * 16;

    // Q fragments (k16 tiles s=0..3)
    const uint32_t* qh32 = (const uint32_t*)qhi;
    const uint32_t* ql32 = (const uint32_t*)qlo;
    size_t r0 = (size_t)(b * S_ + q0 + w16 + g) * 1024 + h * 32;
    size_t r1 = r0 + 8 * 1024;
    uint32_t Qh[4][4], Ql[4][4];
#pragma unroll
    for (int s = 0; s < 4; s++) {
        int w0 = 8 * s + c;
        Qh[s][0] = qh32[r0 + w0];     Qh[s][1] = qh32[r1 + w0];
        Qh[s][2] = qh32[r0 + w0 + 4]; Qh[s][3] = qh32[r1 + w0 + 4];
        Ql[s][0] = ql32[r0 + w0];     Ql[s][1] = ql32[r1 + w0];
        Ql[s][2] = ql32[r0 + w0 + 4]; Ql[s][3] = ql32[r1 + w0 + 4];
    }

    const uint4* kh4 = (const uint4*)khi;
    const uint4* kl4 = (const uint4*)klo;
    const uint4* vh4 = (const uint4*)vthi;
    const uint4* vl4 = (const uint4*)vtlo;

    float m_lo = -1e30f, m_hi = -1e30f, l_lo = 0.f, l_hi = 0.f;
    float4 acc[8];
#pragma unroll
    for (int nt = 0; nt < 8; nt++) acc[nt] = make_float4(0.f, 0.f, 0.f, 0.f);

    const int trow = tid & 63;
    const int tch0 = tid >> 6;

    for (int kv0 = 0; kv0 < S_; kv0 += 64) {
        __syncthreads();
#pragma unroll
        for (int p = 0; p < 2; p++) {
            int ch = tch0 + 4 * p;
            size_t kg4 = (size_t)(b * S_ + kv0 + trow) * 256 + h * 8 + ch;
            size_t vg4 = (((size_t)(b * H_ + h) * 64 + trow) * 1024 + (kv0 >> 1)) / 4 + ch;
            int so = SW(trow, ch);
            *(uint4*)&sKh[so] = kh4[kg4];
            *(uint4*)&sKl[so] = kl4[kg4];
            *(uint4*)&sVh[so] = vh4[vg4];
            *(uint4*)&sVl[so] = vl4[vg4];
        }
        __syncthreads();

        // scores
        float4 sf[8];
#pragma unroll
        for (int nt = 0; nt < 8; nt++) sf[nt] = make_float4(0.f, 0.f, 0.f, 0.f);
#pragma unroll
        for (int s = 0; s < 4; s++) {
#pragma unroll
            for (int nt = 0; nt < 8; nt++) {
                int n = nt * 8 + g;
                uint32_t bh0 = sKh[SW(n, 2*s) + c],   bh1 = sKh[SW(n, 2*s+1) + c];
                uint32_t bl0 = sKl[SW(n, 2*s) + c],   bl1 = sKl[SW(n, 2*s+1) + c];
                mma_bf16(sf[nt], Qh[s][0], Qh[s][1], Qh[s][2], Qh[s][3], bh0, bh1);
                mma_bf16(sf[nt], Qh[s][0], Qh[s][1], Qh[s][2], Qh[s][3], bl0, bl1);
                mma_bf16(sf[nt], Ql[s][0], Ql[s][1], Ql[s][2], Ql[s][3], bh0, bh1);
            }
        }

        // warp-local online softmax (rows g, g+8)
        float tlo = -1e30f, thi = -1e30f;
#pragma unroll
        for (int nt = 0; nt < 8; nt++) {
            tlo = fmaxf(tlo, fmaxf(sf[nt].x, sf[nt].y));
            thi = fmaxf(thi, fmaxf(sf[nt].z, sf[nt].w));
        }
        tlo = fmaxf(tlo, __shfl_xor_sync(0xffffffffu, tlo, 1));
        tlo = fmaxf(tlo, __shfl_xor_sync(0xffffffffu, tlo, 2));
        thi = fmaxf(thi, __shfl_xor_sync(0xffffffffu, thi, 1));
        thi = fmaxf(thi, __shfl_xor_sync(0xffffffffu, thi, 2));

        float mnlo = fmaxf(m_lo, tlo), mnhi = fmaxf(m_hi, thi);
        float corlo = __expf(m_lo - mnlo), corhi = __expf(m_hi - mnhi);
        float slo = 0.f, shi = 0.f;
#pragma unroll
        for (int nt = 0; nt < 8; nt++) {
            sf[nt].x = __expf(sf[nt].x - mnlo);
            sf[nt].y = __expf(sf[nt].y - mnlo);
            sf[nt].z = __expf(sf[nt].z - mnhi);
            sf[nt].w = __expf(sf[nt].w - mnhi);
            slo += sf[nt].x + sf[nt].y;
            shi += sf[nt].z + sf[nt].w;
        }
        slo += __shfl_xor_sync(0xffffffffu, slo, 1);
        slo += __shfl_xor_sync(0xffffffffu, slo, 2);
        shi += __shfl_xor_sync(0xffffffffu, shi, 1);
        shi += __shfl_xor_sync(0xffffffffu, shi, 2);
        l_lo = l_lo * corlo + slo;
        l_hi = l_hi * corhi + shi;
        m_lo = mnlo; m_hi = mnhi;
#pragma unroll
        for (int nt = 0; nt < 8; nt++) {
            acc[nt].x *= corlo; acc[nt].y *= corlo;
            acc[nt].z *= corhi; acc[nt].w *= corhi;
        }

        // PV: A fragments direct from score regs
#pragma unroll
        for (int s = 0; s < 4; s++) {
            uint32_t ah0, al0, ah1, al1, ah2, al2, ah3, al3;
            split2(sf[2*s].x,   sf[2*s].y,   ah0, al0);
            split2(sf[2*s].z,   sf[2*s].w,   ah1, al1);
            split2(sf[2*s+1].x, sf[2*s+1].y, ah2, al2);
            split2(sf[2*s+1].z, sf[2*s+1].w, ah3, al3);
#pragma unroll
            for (int nt = 0; nt < 8; nt++) {
                int n = nt * 8 + g;
                uint32_t vh0 = sVh[SW(n, 2*s) + c], vh1 = sVh[SW(n, 2*s+1) + c];
                uint32_t vl0 = sVl[SW(n, 2*s) + c], vl1 = sVl[SW(n, 2*s+1) + c];
                mma_bf16(acc[nt], ah0, ah1, ah2, ah3, vh0, vh1);
                mma_bf16(acc[nt], ah0, ah1, ah2, ah3, vl0, vl1);
                mma_bf16(acc[nt], al0, al1, al2, al3, vh0, vh1);
            }
        }
    }

    // epilogue: normalize + split to bf16 hi/lo for out-proj
    float ilo = 1.f / l_lo, ihi = 1.f / l_hi;
    uint32_t* ah32 = (uint32_t*)atthi;
    uint32_t* al32 = (uint32_t*)attlo;
    size_t ob0 = (size_t)(b * S_ + q0 + w16 + g) * 1024 + h * 32;
    size_t ob1 = ob0 + 8 * 1024;
#pragma unroll
    for (int nt = 0; nt < 8; nt++) {
        uint32_t h0, l0, h1, l1;
        split2(acc[nt].x * ilo, acc[nt].y * ilo, h0, l0);
        split2(acc[nt].z * ihi, acc[nt].w * ihi, h1, l1);
        ah32[ob0 + nt * 4 + c] = h0; al32[ob0 + nt * 4 + c] = l0;
        ah32[ob1 + nt * 4 + c] = h1; al32[ob1 + nt * 4 + c] = l1;
    }
}

// ---------------------------------------------------------------------------
extern "C" void kernel_launch(void* const* d_in, const int* in_sizes, int n_in,
                              void* d_out, int out_size)
{
    const float* x     = (const float*)d_in[0];
    const float* rope  = (const float*)d_in[1];
    const float* w_qkv = (const float*)d_in[2];
    const float* w_out = (const float*)d_in[3];
    const float* qg    = (const float*)d_in[4];
    const float* qb    = (const float*)d_in[5];
    const float* kg    = (const float*)d_in[6];
    const float* kb    = (const float*)d_in[7];
    float* out = (float*)d_out;

    cudaFuncSetAttribute(gemm_bf16x3, cudaFuncAttributeMaxDynamicSharedMemorySize, GEMM_SMEM);

    float* qkv; cudaGetSymbolAddress((void**)&qkv, g_qkv);
    __nv_bfloat16 *xhi, *xlo, *wqhi, *wqlo, *wohi, *wolo;
    __nv_bfloat16 *qhi, *qlo, *khi, *klo, *vthi, *vtlo, *athi, *atlo;
    cudaGetSymbolAddress((void**)&xhi,  g_xhi);  cudaGetSymbolAddress((void**)&xlo,  g_xlo);
    cudaGetSymbolAddress((void**)&wqhi, g_wqhi); cudaGetSymbolAddress((void**)&wqlo, g_wqlo);
    cudaGetSymbolAddress((void**)&wohi, g_wohi); cudaGetSymbolAddress((void**)&wolo, g_wolo);
    cudaGetSymbolAddress((void**)&qhi,  g_qhi);  cudaGetSymbolAddress((void**)&qlo,  g_qlo);
    cudaGetSymbolAddress((void**)&khi,  g_khi);  cudaGetSymbolAddress((void**)&klo,  g_klo);
    cudaGetSymbolAddress((void**)&vthi, g_vthi); cudaGetSymbolAddress((void**)&vtlo, g_vtlo);
    cudaGetSymbolAddress((void**)&athi, g_atthi);cudaGetSymbolAddress((void**)&atlo, g_attlo);

    // 0) split inputs/weights
    split_kernel<<<(BS * C_ / 4) / 256, 256>>>(x, xhi, xlo, BS * C_ / 4);
    split_kernel<<<(C3 * C_ / 4) / 256, 256>>>(w_qkv, wqhi, wqlo, C3 * C_ / 4);
    split_kernel<<<(C_ * C_ / 4) / 256, 256>>>(w_out, wohi, wolo, C_ * C_ / 4);

    // 1) QKV projection (fp32 out)
    gemm_bf16x3<<<dim3(C3 / 128, BS / 128), 256, GEMM_SMEM>>>(
        xhi, xlo, wqhi, wqlo, qkv, BS, C3, C_);

    // 2) LN + rotary -> split q/k
    ln_rope_kernel<<<(BS * H_ * 2) / 8, 256>>>(qkv, rope, qg, qb, kg, kb, qhi, qlo, khi, klo);

    // 3) V transpose + split
    vt_kernel<<<dim3(S_ / 64, H_, B_), 256>>>(qkv, vthi, vtlo);

    // 4) flash attention -> split att
    attn_bf16x3<<<dim3(S_ / 128, H_, B_), 256>>>(qhi, qlo, khi, klo, vthi, vtlo, athi, atlo);

    // 5) output projection (fp32 out)
    gemm_bf16x3<<<dim3(C_ / 128, BS / 128), 256, GEMM_SMEM>>>(
        athi, atlo, wohi, wolo, out, BS, C_, C_);
}

// round 7
// speedup vs baseline: 3.3210x; 1.1219x over previous
#include <cuda_runtime.h>
#include <cuda_bf16.h>
#include <cstdint>
#include <math.h>

#define B_ 2
#define S_ 2048
#define C_ 2048
#define H_ 32
#define C3 6144
#define BS (B_*S_)

// Scratch (allocation-free device globals)
__device__ float g_qkv[BS * C3];
__device__ __nv_bfloat16 g_xhi[BS * C_],  g_xlo[BS * C_];
__device__ __nv_bfloat16 g_wqhi[C3 * C_], g_wqlo[C3 * C_];
__device__ __nv_bfloat16 g_wohi[C_ * C_], g_wolo[C_ * C_];
__device__ __nv_bfloat16 g_qhi[BS * C_],  g_qlo[BS * C_];
__device__ __nv_bfloat16 g_khi[BS * C_],  g_klo[BS * C_];
__device__ __nv_bfloat16 g_vthi[(size_t)B_ * H_ * 64 * S_], g_vtlo[(size_t)B_ * H_ * 64 * S_];
__device__ __nv_bfloat16 g_atthi[BS * C_], g_attlo[BS * C_];

__device__ __forceinline__ void mma_bf16(float4 &d,
    uint32_t a0, uint32_t a1, uint32_t a2, uint32_t a3, uint32_t b0, uint32_t b1)
{
    asm volatile("mma.sync.aligned.m16n8k16.row.col.f32.bf16.bf16.f32 "
        "{%0,%1,%2,%3}, {%4,%5,%6,%7}, {%8,%9}, {%0,%1,%2,%3};"
        : "+f"(d.x), "+f"(d.y), "+f"(d.z), "+f"(d.w)
        : "r"(a0), "r"(a1), "r"(a2), "r"(a3), "r"(b0), "r"(b1));
}

__device__ __forceinline__ uint4 ldm_x4(uint32_t addr) {
    uint4 r;
    asm volatile("ldmatrix.sync.aligned.m8n8.x4.shared.b16 {%0,%1,%2,%3}, [%4];"
        : "=r"(r.x), "=r"(r.y), "=r"(r.z), "=r"(r.w) : "r"(addr));
    return r;
}

__device__ __forceinline__ void cp16(uint32_t saddr, const void* g) {
    asm volatile("cp.async.cg.shared.global [%0], [%1], 16;" :: "r"(saddr), "l"(g));
}
#define CP_COMMIT() asm volatile("cp.async.commit_group;")

__device__ __forceinline__ uint32_t pack2(__nv_bfloat16 a, __nv_bfloat16 b) {
    __nv_bfloat162 t; t.x = a; t.y = b;
    return *reinterpret_cast<uint32_t*>(&t);
}

__device__ __forceinline__ void split2(float a, float b, uint32_t &hi, uint32_t &lo) {
    __nv_bfloat16 ha = __float2bfloat16_rn(a), hb = __float2bfloat16_rn(b);
    __nv_bfloat16 la = __float2bfloat16_rn(a - __bfloat162float(ha));
    __nv_bfloat16 lb = __float2bfloat16_rn(b - __bfloat162float(hb));
    hi = pack2(ha, hb); lo = pack2(la, lb);
}

// fp32 -> hi/lo bf16 split
__global__ __launch_bounds__(256) void split_kernel(
    const float* __restrict__ in, __nv_bfloat16* __restrict__ hi,
    __nv_bfloat16* __restrict__ lo, int n4)
{
    int i = blockIdx.x * blockDim.x + threadIdx.x;
    if (i >= n4) return;
    float4 v = ((const float4*)in)[i];
    uint32_t h0, l0, h1, l1;
    split2(v.x, v.y, h0, l0);
    split2(v.z, v.w, h1, l1);
    uint32_t* hi32 = (uint32_t*)hi;
    uint32_t* lo32 = (uint32_t*)lo;
    hi32[2*i] = h0; hi32[2*i+1] = h1;
    lo32[2*i] = l0; lo32[2*i+1] = l1;
}

// ---------------------------------------------------------------------------
// bf16x3 GEMM v2: cp.async 3-stage + ldmatrix.
// Block 128x128, BK=32, 256 thr = 8 warps (2m x 4n), warp tile 64x32.
// Smem row = 64B = 4 chunks of 16B; chunk ch stored at phys = ch ^ ((row>>1)&3).
// Stage = [Ahi|Alo|Bhi|Blo] x 8KB = 32KB; 3 stages = 96KB dynamic.
// ---------------------------------------------------------------------------
#define GSTAGES 3
#define GSTAGE_BYTES (4 * 8192)
#define GEMM_SMEM (GSTAGES * GSTAGE_BYTES)

__global__ __launch_bounds__(256, 2) void gemm_bf16x3(
    const __nv_bfloat16* __restrict__ Ahi, const __nv_bfloat16* __restrict__ Alo,
    const __nv_bfloat16* __restrict__ Bhi, const __nv_bfloat16* __restrict__ Blo,
    float* __restrict__ C, int M, int N, int K)
{
    extern __shared__ uint8_t gsm8[];
    const uint32_t sbase = (uint32_t)__cvta_generic_to_shared(gsm8);

    const int tid  = threadIdx.x;
    const int lane = tid & 31, wid = tid >> 5;
    const int g = lane >> 2, c = lane & 3;
    const int wm = wid >> 2, wn = wid & 3;
    const int m0 = blockIdx.y * 128, n0 = blockIdx.x * 128;
    const int rsu = K >> 3;            // uint4 per gmem row

    // cp.async mapping: thread -> (row, 2 chunks)
    const int crow = tid >> 1;
    const int cc0  = (tid & 1) * 2;
    const int csw  = (crow >> 1) & 3;
    const uint32_t soff0 = crow * 64 + ((cc0 ^ csw) << 4);
    const uint32_t soff1 = crow * 64 + (((cc0 + 1) ^ csw) << 4);
    const uint4* gAh = (const uint4*)Ahi + (size_t)(m0 + crow) * rsu + cc0;
    const uint4* gAl = (const uint4*)Alo + (size_t)(m0 + crow) * rsu + cc0;
    const uint4* gBh = (const uint4*)Bhi + (size_t)(n0 + crow) * rsu + cc0;
    const uint4* gBl = (const uint4*)Blo + (size_t)(n0 + crow) * rsu + cc0;

    // fragment (ldmatrix) per-lane offsets within an array
    const int sub  = lane >> 3;
    const int arow = wm * 64 + ((sub & 1) << 3) + (lane & 7);
    const int chA  = sub >> 1;                               // k16 tile 0 chunk
    const uint32_t aoffA0 = arow * 64 + ((chA ^ ((arow >> 1) & 3)) << 4);
    const uint32_t aoffA1 = aoffA0 ^ 32;                     // k16 tile 1 (ch+2)
    const int brow = wn * 32 + (lane & 7);
    const uint32_t aoffB = brow * 64 + (((lane >> 3) ^ ((brow >> 1) & 3)) << 4);

    float4 d[4][4];
#pragma unroll
    for (int i = 0; i < 4; i++)
#pragma unroll
        for (int j = 0; j < 4; j++) d[i][j] = make_float4(0.f, 0.f, 0.f, 0.f);

    auto issue = [&](int tile) {
        const uint32_t sb = sbase + (tile % GSTAGES) * GSTAGE_BYTES;
        const int kc = tile * 4;
        cp16(sb + soff0,         gAh + kc);     cp16(sb + soff1,         gAh + kc + 1);
        cp16(sb + 8192  + soff0, gAl + kc);     cp16(sb + 8192  + soff1, gAl + kc + 1);
        cp16(sb + 16384 + soff0, gBh + kc);     cp16(sb + 16384 + soff1, gBh + kc + 1);
        cp16(sb + 24576 + soff0, gBl + kc);     cp16(sb + 24576 + soff1, gBl + kc + 1);
    };

    const int nit = K >> 5;
    issue(0); CP_COMMIT();
    issue(1); CP_COMMIT();

    for (int it = 0; it < nit; it++) {
        if (it + 1 < nit) { asm volatile("cp.async.wait_group 1;"); }
        else              { asm volatile("cp.async.wait_group 0;"); }
        __syncthreads();
        if (it + 2 < nit) { issue(it + 2); CP_COMMIT(); }

        const uint32_t sb  = sbase + (it % GSTAGES) * GSTAGE_BYTES;
        const uint32_t bA  = sb + aoffA0;
        const uint32_t bA1 = sb + aoffA1;
        const uint32_t bB  = sb + 16384 + aoffB;

        uint4 bh[4], bl[4];
#pragma unroll
        for (int in_ = 0; in_ < 4; in_++) {
            bh[in_] = ldm_x4(bB + in_ * 512);
            bl[in_] = ldm_x4(bB + 8192 + in_ * 512);
        }
#pragma unroll
        for (int im = 0; im < 4; im++) {
            uint4 ah0 = ldm_x4(bA  + im * 1024);          // k16 tile 0: a0..a3
            uint4 ah1 = ldm_x4(bA1 + im * 1024);          // k16 tile 1
            uint4 al0 = ldm_x4(bA  + 8192 + im * 1024);
            uint4 al1 = ldm_x4(bA1 + 8192 + im * 1024);
#pragma unroll
            for (int in_ = 0; in_ < 4; in_++) {
                mma_bf16(d[im][in_], ah0.x, ah0.y, ah0.z, ah0.w, bh[in_].x, bh[in_].y);
                mma_bf16(d[im][in_], ah0.x, ah0.y, ah0.z, ah0.w, bl[in_].x, bl[in_].y);
                mma_bf16(d[im][in_], al0.x, al0.y, al0.z, al0.w, bh[in_].x, bh[in_].y);
                mma_bf16(d[im][in_], ah1.x, ah1.y, ah1.z, ah1.w, bh[in_].z, bh[in_].w);
                mma_bf16(d[im][in_], ah1.x, ah1.y, ah1.z, ah1.w, bl[in_].z, bl[in_].w);
                mma_bf16(d[im][in_], al1.x, al1.y, al1.z, al1.w, bh[in_].z, bh[in_].w);
            }
        }
        __syncthreads();
    }

#pragma unroll
    for (int im = 0; im < 4; im++)
#pragma unroll
        for (int in_ = 0; in_ < 4; in_++) {
            int row = m0 + wm * 64 + im * 16 + g;
            int col = n0 + wn * 32 + in_ * 8 + 2 * c;
            *(float2*)&C[(size_t)row * N + col]       = make_float2(d[im][in_].x, d[im][in_].y);
            *(float2*)&C[(size_t)(row + 8) * N + col] = make_float2(d[im][in_].z, d[im][in_].w);
        }
}

// ---------------------------------------------------------------------------
// LN (per-head) + rotary; q pre-scaled by 1/8; writes split bf16 q/k.
// ---------------------------------------------------------------------------
__global__ __launch_bounds__(256) void ln_rope_kernel(
    const float* __restrict__ qkv, const float* __restrict__ rope,
    const float* __restrict__ qg, const float* __restrict__ qb,
    const float* __restrict__ kg, const float* __restrict__ kb,
    __nv_bfloat16* __restrict__ qhi, __nv_bfloat16* __restrict__ qlo,
    __nv_bfloat16* __restrict__ khi, __nv_bfloat16* __restrict__ klo)
{
    int wid  = (blockIdx.x * blockDim.x + threadIdx.x) >> 5;
    int lane = threadIdx.x & 31;
    int which = wid & 1;
    int rowh  = wid >> 1;
    int h  = rowh & 31;
    int bs = rowh >> 5;
    int s  = bs & (S_ - 1);

    const float* p = qkv + (size_t)bs * C3 + h * 192 + which * 64;
    float x0 = p[lane];
    float x1 = p[lane + 32];

    float sum = x0 + x1;
#pragma unroll
    for (int off = 16; off > 0; off >>= 1) sum += __shfl_xor_sync(0xffffffffu, sum, off);
    float mean = sum * (1.0f / 64.0f);
    float d0 = x0 - mean, d1 = x1 - mean;
    float vs = d0 * d0 + d1 * d1;
#pragma unroll
    for (int off = 16; off > 0; off >>= 1) vs += __shfl_xor_sync(0xffffffffu, vs, off);
    float rstd = rsqrtf(vs * (1.0f / 64.0f) + 1e-5f);

    const float* gm = which ? kg : qg;
    const float* bt = which ? kb : qb;
    float y0 = d0 * rstd * gm[lane]      + bt[lane];
    float y1 = d1 * rstd * gm[lane + 32] + bt[lane + 32];

    float pr0 = __shfl_xor_sync(0xffffffffu, y0, 1);
    float pr1 = __shfl_xor_sync(0xffffffffu, y1, 1);
    int j = lane & 1;
    const float* rb = rope + s * 128;

    int i0 = lane >> 1;
    float e0 = j ? pr0 : y0;
    float o0 = j ? y0 : pr0;
    float out0 = rb[i0 * 4 + j * 2 + 0] * e0 + rb[i0 * 4 + j * 2 + 1] * o0;

    int i1 = (lane + 32) >> 1;
    float e1 = j ? pr1 : y1;
    float o1 = j ? y1 : pr1;
    float out1 = rb[i1 * 4 + j * 2 + 0] * e1 + rb[i1 * 4 + j * 2 + 1] * o1;

    if (which == 0) { out0 *= 0.125f; out1 *= 0.125f; }

    __nv_bfloat16* hi = which ? khi : qhi;
    __nv_bfloat16* lo = which ? klo : qlo;
    size_t base = (size_t)bs * C_ + h * 64;
    __nv_bfloat16 h0 = __float2bfloat16_rn(out0);
    __nv_bfloat16 h1 = __float2bfloat16_rn(out1);
    hi[base + lane]      = h0;
    hi[base + lane + 32] = h1;
    lo[base + lane]      = __float2bfloat16_rn(out0 - __bfloat162float(h0));
    lo[base + lane + 32] = __float2bfloat16_rn(out1 - __bfloat162float(h1));
}

// ---------------------------------------------------------------------------
// V transpose + split: qkv v-slice [b][s][h][d] -> vt[b][h][d][s] bf16 hi/lo
// ---------------------------------------------------------------------------
__global__ __launch_bounds__(256) void vt_kernel(
    const float* __restrict__ qkv,
    __nv_bfloat16* __restrict__ vthi, __nv_bfloat16* __restrict__ vtlo)
{
    __shared__ __nv_bfloat16 shi[64][72];
    __shared__ __nv_bfloat16 slo[64][72];

    const int tid = threadIdx.x;
    const int s0 = blockIdx.x * 64, h = blockIdx.y, b = blockIdx.z;
    const int tok = tid >> 2, q = tid & 3;

#pragma unroll
    for (int it = 0; it < 4; it++) {
        int dd = q * 16 + it * 4;
        float4 v = *(const float4*)&qkv[(size_t)(b * S_ + s0 + tok) * C3 + h * 192 + 128 + dd];
        float vv[4] = {v.x, v.y, v.z, v.w};
#pragma unroll
        for (int j = 0; j < 4; j++) {
            __nv_bfloat16 hb = __float2bfloat16_rn(vv[j]);
            shi[dd + j][tok] = hb;
            slo[dd + j][tok] = __float2bfloat16_rn(vv[j] - __bfloat162float(hb));
        }
    }
    __syncthreads();

    const int dr = tid >> 2, cq = tid & 3;
    size_t gbase = ((size_t)(b * H_ + h) * 64 + dr) * S_ + s0 + cq * 16;
#pragma unroll
    for (int half = 0; half < 2; half++) {
        *(uint4*)&vthi[gbase + half * 8] = *(const uint4*)&shi[dr][cq * 16 + half * 8];
        *(uint4*)&vtlo[gbase + half * 8] = *(const uint4*)&slo[dr][cq * 16 + half * 8];
    }
}

// ---------------------------------------------------------------------------
// Flash attention, bf16x3, cp.async double-buffered K/V tiles.
// 128 q rows per block, 8 warps, warp-local softmax. Compute layout as R5.
// Dynamic smem: 2 stages x [Kh|Kl|Vh|Vl] x 8KB = 64KB.
// ---------------------------------------------------------------------------
#define SW(row, ch) ((row) * 32 + (((ch) ^ ((row) & 7)) << 2))
#define ATT_SMEM (2 * 4 * 8192)

__global__ __launch_bounds__(256) void attn_bf16x3(
    const __nv_bfloat16* __restrict__ qhi, const __nv_bfloat16* __restrict__ qlo,
    const __nv_bfloat16* __restrict__ khi, const __nv_bfloat16* __restrict__ klo,
    const __nv_bfloat16* __restrict__ vthi, const __nv_bfloat16* __restrict__ vtlo,
    __nv_bfloat16* __restrict__ atthi, __nv_bfloat16* __restrict__ attlo)
{
    extern __shared__ uint8_t asm8[];
    uint32_t* dsmw = (uint32_t*)asm8;
    const uint32_t sabase = (uint32_t)__cvta_generic_to_shared(asm8);

    const int tid = threadIdx.x, lane = tid & 31, wid = tid >> 5;
    const int g = lane >> 2, c = lane & 3;
    const int q0 = blockIdx.x * 128;
    const int h = blockIdx.y, b = blockIdx.z;
    const int w16 = wid * 16;

    // Q fragments
    const uint32_t* qh32 = (const uint32_t*)qhi;
    const uint32_t* ql32 = (const uint32_t*)qlo;
    size_t r0 = (size_t)(b * S_ + q0 + w16 + g) * 1024 + h * 32;
    size_t r1 = r0 + 8 * 1024;
    uint32_t Qh[4][4], Ql[4][4];
#pragma unroll
    for (int s = 0; s < 4; s++) {
        int w0 = 8 * s + c;
        Qh[s][0] = qh32[r0 + w0];     Qh[s][1] = qh32[r1 + w0];
        Qh[s][2] = qh32[r0 + w0 + 4]; Qh[s][3] = qh32[r1 + w0 + 4];
        Ql[s][0] = ql32[r0 + w0];     Ql[s][1] = ql32[r1 + w0];
        Ql[s][2] = ql32[r0 + w0 + 4]; Ql[s][3] = ql32[r1 + w0 + 4];
    }

    const uint4* kh4 = (const uint4*)khi;
    const uint4* kl4 = (const uint4*)klo;
    const uint4* vh4 = (const uint4*)vthi;
    const uint4* vl4 = (const uint4*)vtlo;

    float m_lo = -1e30f, m_hi = -1e30f, l_lo = 0.f, l_hi = 0.f;
    float4 acc[8];
#pragma unroll
    for (int nt = 0; nt < 8; nt++) acc[nt] = make_float4(0.f, 0.f, 0.f, 0.f);

    const int trow = tid & 63;
    const int tch0 = tid >> 6;

    auto issueA = [&](int i) {
        const uint32_t sb = sabase + (i & 1) * 32768;
        const int kv0 = i * 64;
        const size_t kg = (size_t)(b * S_ + kv0 + trow) * 256 + h * 8;
        const size_t vg = ((size_t)(b * H_ + h) * 64 + trow) * 256 + (size_t)(kv0 >> 3);
#pragma unroll
        for (int p = 0; p < 2; p++) {
            const int ch = tch0 + 4 * p;
            const uint32_t so = trow * 128 + ((ch ^ (trow & 7)) << 4);
            cp16(sb + so,         kh4 + kg + ch);
            cp16(sb + 8192  + so, kl4 + kg + ch);
            cp16(sb + 16384 + so, vh4 + vg + ch);
            cp16(sb + 24576 + so, vl4 + vg + ch);
        }
    };

    issueA(0); CP_COMMIT();

    for (int i = 0; i < 32; i++) {
        asm volatile("cp.async.wait_group 0;");
        __syncthreads();
        if (i + 1 < 32) { issueA(i + 1); CP_COMMIT(); }

        const uint32_t* sKh = dsmw + ((i & 1) * 4 + 0) * 2048;
        const uint32_t* sKl = dsmw + ((i & 1) * 4 + 1) * 2048;
        const uint32_t* sVh = dsmw + ((i & 1) * 4 + 2) * 2048;
        const uint32_t* sVl = dsmw + ((i & 1) * 4 + 3) * 2048;

        // scores
        float4 sf[8];
#pragma unroll
        for (int nt = 0; nt < 8; nt++) sf[nt] = make_float4(0.f, 0.f, 0.f, 0.f);
#pragma unroll
        for (int s = 0; s < 4; s++) {
#pragma unroll
            for (int nt = 0; nt < 8; nt++) {
                int n = nt * 8 + g;
                uint32_t bh0 = sKh[SW(n, 2*s) + c],   bh1 = sKh[SW(n, 2*s+1) + c];
                uint32_t bl0 = sKl[SW(n, 2*s) + c],   bl1 = sKl[SW(n, 2*s+1) + c];
                mma_bf16(sf[nt], Qh[s][0], Qh[s][1], Qh[s][2], Qh[s][3], bh0, bh1);
                mma_bf16(sf[nt], Qh[s][0], Qh[s][1], Qh[s][2], Qh[s][3], bl0, bl1);
                mma_bf16(sf[nt], Ql[s][0], Ql[s][1], Ql[s][2], Ql[s][3], bh0, bh1);
            }
        }

        // warp-local online softmax (rows g, g+8)
        float tlo = -1e30f, thi = -1e30f;
#pragma unroll
        for (int nt = 0; nt < 8; nt++) {
            tlo = fmaxf(tlo, fmaxf(sf[nt].x, sf[nt].y));
            thi = fmaxf(thi, fmaxf(sf[nt].z, sf[nt].w));
        }
        tlo = fmaxf(tlo, __shfl_xor_sync(0xffffffffu, tlo, 1));
        tlo = fmaxf(tlo, __shfl_xor_sync(0xffffffffu, tlo, 2));
        thi = fmaxf(thi, __shfl_xor_sync(0xffffffffu, thi, 1));
        thi = fmaxf(thi, __shfl_xor_sync(0xffffffffu, thi, 2));

        float mnlo = fmaxf(m_lo, tlo), mnhi = fmaxf(m_hi, thi);
        float corlo = __expf(m_lo - mnlo), corhi = __expf(m_hi - mnhi);
        float slo = 0.f, shi = 0.f;
#pragma unroll
        for (int nt = 0; nt < 8; nt++) {
            sf[nt].x = __expf(sf[nt].x - mnlo);
            sf[nt].y = __expf(sf[nt].y - mnlo);
            sf[nt].z = __expf(sf[nt].z - mnhi);
            sf[nt].w = __expf(sf[nt].w - mnhi);
            slo += sf[nt].x + sf[nt].y;
            shi += sf[nt].z + sf[nt].w;
        }
        slo += __shfl_xor_sync(0xffffffffu, slo, 1);
        slo += __shfl_xor_sync(0xffffffffu, slo, 2);
        shi += __shfl_xor_sync(0xffffffffu, shi, 1);
        shi += __shfl_xor_sync(0xffffffffu, shi, 2);
        l_lo = l_lo * corlo + slo;
        l_hi = l_hi * corhi + shi;
        m_lo = mnlo; m_hi = mnhi;
#pragma unroll
        for (int nt = 0; nt < 8; nt++) {
            acc[nt].x *= corlo; acc[nt].y *= corlo;
            acc[nt].z *= corhi; acc[nt].w *= corhi;
        }

        // PV: A fragments direct from score regs
#pragma unroll
        for (int s = 0; s < 4; s++) {
            uint32_t ah0, al0, ah1, al1, ah2, al2, ah3, al3;
            split2(sf[2*s].x,   sf[2*s].y,   ah0, al0);
            split2(sf[2*s].z,   sf[2*s].w,   ah1, al1);
            split2(sf[2*s+1].x, sf[2*s+1].y, ah2, al2);
            split2(sf[2*s+1].z, sf[2*s+1].w, ah3, al3);
#pragma unroll
            for (int nt = 0; nt < 8; nt++) {
                int n = nt * 8 + g;
                uint32_t vh0 = sVh[SW(n, 2*s) + c], vh1 = sVh[SW(n, 2*s+1) + c];
                uint32_t vl0 = sVl[SW(n, 2*s) + c], vl1 = sVl[SW(n, 2*s+1) + c];
                mma_bf16(acc[nt], ah0, ah1, ah2, ah3, vh0, vh1);
                mma_bf16(acc[nt], ah0, ah1, ah2, ah3, vl0, vl1);
                mma_bf16(acc[nt], al0, al1, al2, al3, vh0, vh1);
            }
        }
    }

    // epilogue: normalize + split to bf16 hi/lo for out-proj
    float ilo = 1.f / l_lo, ihi = 1.f / l_hi;
    uint32_t* ah32 = (uint32_t*)atthi;
    uint32_t* al32 = (uint32_t*)attlo;
    size_t ob0 = (size_t)(b * S_ + q0 + w16 + g) * 1024 + h * 32;
    size_t ob1 = ob0 + 8 * 1024;
#pragma unroll
    for (int nt = 0; nt < 8; nt++) {
        uint32_t h0, l0, h1, l1;
        split2(acc[nt].x * ilo, acc[nt].y * ilo, h0, l0);
        split2(acc[nt].z * ihi, acc[nt].w * ihi, h1, l1);
        ah32[ob0 + nt * 4 + c] = h0; al32[ob0 + nt * 4 + c] = l0;
        ah32[ob1 + nt * 4 + c] = h1; al32[ob1 + nt * 4 + c] = l1;
    }
}

// ---------------------------------------------------------------------------
extern "C" void kernel_launch(void* const* d_in, const int* in_sizes, int n_in,
                              void* d_out, int out_size)
{
    const float* x     = (const float*)d_in[0];
    const float* rope  = (const float*)d_in[1];
    const float* w_qkv = (const float*)d_in[2];
    const float* w_out = (const float*)d_in[3];
    const float* qg    = (const float*)d_in[4];
    const float* qb    = (const float*)d_in[5];
    const float* kg    = (const float*)d_in[6];
    const float* kb    = (const float*)d_in[7];
    float* out = (float*)d_out;

    cudaFuncSetAttribute(gemm_bf16x3, cudaFuncAttributeMaxDynamicSharedMemorySize, GEMM_SMEM);
    cudaFuncSetAttribute(attn_bf16x3, cudaFuncAttributeMaxDynamicSharedMemorySize, ATT_SMEM);

    float* qkv; cudaGetSymbolAddress((void**)&qkv, g_qkv);
    __nv_bfloat16 *xhi, *xlo, *wqhi, *wqlo, *wohi, *wolo;
    __nv_bfloat16 *qhi, *qlo, *khi, *klo, *vthi, *vtlo, *athi, *atlo;
    cudaGetSymbolAddress((void**)&xhi,  g_xhi);  cudaGetSymbolAddress((void**)&xlo,  g_xlo);
    cudaGetSymbolAddress((void**)&wqhi, g_wqhi); cudaGetSymbolAddress((void**)&wqlo, g_wqlo);
    cudaGetSymbolAddress((void**)&wohi, g_wohi); cudaGetSymbolAddress((void**)&wolo, g_wolo);
    cudaGetSymbolAddress((void**)&qhi,  g_qhi);  cudaGetSymbolAddress((void**)&qlo,  g_qlo);
    cudaGetSymbolAddress((void**)&khi,  g_khi);  cudaGetSymbolAddress((void**)&klo,  g_klo);
    cudaGetSymbolAddress((void**)&vthi, g_vthi); cudaGetSymbolAddress((void**)&vtlo, g_vtlo);
    cudaGetSymbolAddress((void**)&athi, g_atthi);cudaGetSymbolAddress((void**)&atlo, g_attlo);

    // 0) split inputs/weights
    split_kernel<<<(BS * C_ / 4) / 256, 256>>>(x, xhi, xlo, BS * C_ / 4);
    split_kernel<<<(C3 * C_ / 4) / 256, 256>>>(w_qkv, wqhi, wqlo, C3 * C_ / 4);
    split_kernel<<<(C_ * C_ / 4) / 256, 256>>>(w_out, wohi, wolo, C_ * C_ / 4);

    // 1) QKV projection (fp32 out)
    gemm_bf16x3<<<dim3(C3 / 128, BS / 128), 256, GEMM_SMEM>>>(
        xhi, xlo, wqhi, wqlo, qkv, BS, C3, C_);

    // 2) LN + rotary -> split q/k
    ln_rope_kernel<<<(BS * H_ * 2) / 8, 256>>>(qkv, rope, qg, qb, kg, kb, qhi, qlo, khi, klo);

    // 3) V transpose + split
    vt_kernel<<<dim3(S_ / 64, H_, B_), 256>>>(qkv, vthi, vtlo);

    // 4) flash attention -> split att
    attn_bf16x3<<<dim3(S_ / 128, H_, B_), 256, ATT_SMEM>>>(
        qhi, qlo, khi, klo, vthi, vtlo, athi, atlo);

    // 5) output projection (fp32 out)
    gemm_bf16x3<<<dim3(C_ / 128, BS / 128), 256, GEMM_SMEM>>>(
        athi, atlo, wohi, wolo, out, BS, C_, C_);
}